// round 5
// baseline (speedup 1.0000x reference)
#include <cuda_runtime.h>
#include <cuda_bf16.h>
#include <math.h>
#include <stdint.h>

#define FULLMASK 0xffffffffu
#define BATCH 2
#define NHEAD 16
#define QLEN  2048
#define KVLEN 4096
#define HID   1024
#define BH    (BATCH * NHEAD)
#define TOPK  32
#define MQ    (BATCH * QLEN)
#define MKV   (BATCH * KVLEN)

typedef __nv_bfloat16 bf16;
typedef __nv_bfloat162 bf162;

// ---------------------------------------------------------------------------
// Scratch
// ---------------------------------------------------------------------------
__device__ float g_qf[(size_t)BH * QLEN * 64];
__device__ float g_kf[(size_t)BH * KVLEN * 64];
__device__ bf16 g_q0[(size_t)BH * QLEN * 64],  g_q1[(size_t)BH * QLEN * 64];
__device__ bf16 g_k0[(size_t)BH * KVLEN * 64], g_k1[(size_t)BH * KVLEN * 64];
__device__ bf16 g_vs0[(size_t)MKV * HID], g_vs1[(size_t)MKV * HID];
__device__ bf16 g_wv0[(size_t)HID * HID], g_wv1[(size_t)HID * HID];
__device__ bf16 g_wo0[(size_t)HID * HID], g_wo1[(size_t)HID * HID];
__device__ float g_v[(size_t)BH * KVLEN * 64];
__device__ bf16 g_at0[(size_t)MQ * HID], g_at1[(size_t)MQ * HID];
__device__ float g_scores[(size_t)BH * QLEN * KVLEN];

// ---------------------------------------------------------------------------
// PTX helpers
// ---------------------------------------------------------------------------
__device__ __forceinline__ uint32_t s2u(const void* p) {
    uint32_t a;
    asm("{ .reg .u64 t; cvta.to.shared.u64 t, %1; cvt.u32.u64 %0, t; }"
        : "=r"(a) : "l"(p));
    return a;
}
__device__ __forceinline__ void cpasync16(uint32_t dst, const void* src) {
    asm volatile("cp.async.cg.shared.global [%0], [%1], 16;" :: "r"(dst), "l"(src));
}
#define CP_COMMIT() asm volatile("cp.async.commit_group;" ::: "memory")
#define CP_WAIT1()  asm volatile("cp.async.wait_group 1;" ::: "memory")

__device__ __forceinline__ void ldsm4(uint32_t* r, uint32_t addr) {
    asm volatile("ldmatrix.sync.aligned.m8n8.x4.shared.b16 {%0,%1,%2,%3}, [%4];"
                 : "=r"(r[0]), "=r"(r[1]), "=r"(r[2]), "=r"(r[3]) : "r"(addr));
}
__device__ __forceinline__ void mma16816(float* c, const uint32_t* a, uint32_t b0, uint32_t b1) {
    asm volatile("mma.sync.aligned.m16n8k16.row.col.f32.bf16.bf16.f32 "
                 "{%0,%1,%2,%3}, {%4,%5,%6,%7}, {%8,%9}, {%0,%1,%2,%3};"
                 : "+f"(c[0]), "+f"(c[1]), "+f"(c[2]), "+f"(c[3])
                 : "r"(a[0]), "r"(a[1]), "r"(a[2]), "r"(a[3]), "r"(b0), "r"(b1));
}

// ---------------------------------------------------------------------------
// split kernel (2-way)
// ---------------------------------------------------------------------------
__global__ void split2_k(const float* __restrict__ s, bf16* __restrict__ o0,
                         bf16* __restrict__ o1, int n4) {
    int i = blockIdx.x * blockDim.x + threadIdx.x;
    if (i >= n4) return;
    float4 x = reinterpret_cast<const float4*>(s)[i];
    bf16 h0[4], h1[4];
#pragma unroll
    for (int e = 0; e < 4; e++) {
        float v = (&x.x)[e];
        h0[e] = __float2bfloat16(v);
        h1[e] = __float2bfloat16(v - __bfloat162float(h0[e]));
    }
    reinterpret_cast<bf162*>(o0)[i * 2]     = __halves2bfloat162(h0[0], h0[1]);
    reinterpret_cast<bf162*>(o0)[i * 2 + 1] = __halves2bfloat162(h0[2], h0[3]);
    reinterpret_cast<bf162*>(o1)[i * 2]     = __halves2bfloat162(h1[0], h1[1]);
    reinterpret_cast<bf162*>(o1)[i * 2 + 1] = __halves2bfloat162(h1[2], h1[3]);
}

// ---------------------------------------------------------------------------
// fp32 FFMA NT GEMM (proven R1 kernel): C = A[M,1024] @ W[1024,1024]^T + bias
// Epilogue: head-split fp32 + 2-split bf16.
// ---------------------------------------------------------------------------
__global__ __launch_bounds__(256, 2)
void gemm_qk(const float* __restrict__ A, const float* __restrict__ Bm,
             const float* __restrict__ bias, float* __restrict__ Cf,
             bf16* __restrict__ o0, bf16* __restrict__ o1, int Lper)
{
    __shared__ float As[16][132];
    __shared__ float Bs[16][132];

    const int tid = threadIdx.x;
    const int tx = tid & 15;
    const int ty = tid >> 4;
    const int m0 = blockIdx.y * 128;
    const int n0 = blockIdx.x * 128;
    const int lrow = tid >> 1;
    const int lcol = (tid & 1) * 8;

    float acc[8][8];
#pragma unroll
    for (int i = 0; i < 8; i++)
#pragma unroll
        for (int j = 0; j < 8; j++) acc[i][j] = 0.f;

    const float* agp = A  + (size_t)(m0 + lrow) * HID + lcol;
    const float* bgp = Bm + (size_t)(n0 + lrow) * HID + lcol;

    for (int k0 = 0; k0 < HID; k0 += 16) {
        float4 a0 = *(const float4*)(agp + k0);
        float4 a1 = *(const float4*)(agp + k0 + 4);
        float4 b0 = *(const float4*)(bgp + k0);
        float4 b1 = *(const float4*)(bgp + k0 + 4);

        __syncthreads();
        As[lcol + 0][lrow] = a0.x; As[lcol + 1][lrow] = a0.y;
        As[lcol + 2][lrow] = a0.z; As[lcol + 3][lrow] = a0.w;
        As[lcol + 4][lrow] = a1.x; As[lcol + 5][lrow] = a1.y;
        As[lcol + 6][lrow] = a1.z; As[lcol + 7][lrow] = a1.w;
        Bs[lcol + 0][lrow] = b0.x; Bs[lcol + 1][lrow] = b0.y;
        Bs[lcol + 2][lrow] = b0.z; Bs[lcol + 3][lrow] = b0.w;
        Bs[lcol + 4][lrow] = b1.x; Bs[lcol + 5][lrow] = b1.y;
        Bs[lcol + 6][lrow] = b1.z; Bs[lcol + 7][lrow] = b1.w;
        __syncthreads();

#pragma unroll
        for (int kk = 0; kk < 16; kk++) {
            float4 xa0 = *(const float4*)&As[kk][ty * 4];
            float4 xa1 = *(const float4*)&As[kk][64 + ty * 4];
            float4 xb0 = *(const float4*)&Bs[kk][tx * 4];
            float4 xb1 = *(const float4*)&Bs[kk][64 + tx * 4];
            float av[8], bv[8];
            av[0] = xa0.x; av[1] = xa0.y; av[2] = xa0.z; av[3] = xa0.w;
            av[4] = xa1.x; av[5] = xa1.y; av[6] = xa1.z; av[7] = xa1.w;
            bv[0] = xb0.x; bv[1] = xb0.y; bv[2] = xb0.z; bv[3] = xb0.w;
            bv[4] = xb1.x; bv[5] = xb1.y; bv[6] = xb1.z; bv[7] = xb1.w;
#pragma unroll
            for (int i = 0; i < 8; i++)
#pragma unroll
                for (int j = 0; j < 8; j++)
                    acc[i][j] = fmaf(av[i], bv[j], acc[i][j]);
        }
    }

#pragma unroll
    for (int i = 0; i < 8; i++) {
        const int m = m0 + ((i < 4) ? (ty * 4 + i) : (64 + ty * 4 + (i - 4)));
        const int b = m / Lper;
        const int mm = m - b * Lper;
#pragma unroll
        for (int j = 0; j < 8; j++) {
            const int n = n0 + ((j < 4) ? (tx * 4 + j) : (64 + tx * 4 + (j - 4)));
            const float val = acc[i][j] + bias[n];
            const int h = n >> 6, d = n & 63;
            const size_t base = (((size_t)b * NHEAD + h) * Lper + mm) * 64 + d;
            Cf[base] = val;
            bf16 h0 = __float2bfloat16(val);
            o0[base] = h0;
            o1[base] = __float2bfloat16(val - __bfloat162float(h0));
        }
    }
}

// ---------------------------------------------------------------------------
// Split-product bf16 NT GEMM (HMMA). NP=3: products (0,1),(1,0),(0,0).
// CTA 128x128, 512 threads, warp tile 64x16, 3-stage cp.async.
// EPI: 1 = fp32 head-split (+bias) [V]; 2 = fp32 linear (+bias) [O];
//      3 = fp32 *0.125 -> scores[z].
// ---------------------------------------------------------------------------
template<int CPP, int EPI>
__global__ __launch_bounds__(512, 1)
void mma_gemm(const bf16* __restrict__ A0, const bf16* __restrict__ A1,
              const bf16* __restrict__ B0, const bf16* __restrict__ B1,
              const float* __restrict__ bias, float* __restrict__ co,
              int Lper, long long zA, long long zB)
{
    constexpr int K  = CPP * 32;
    constexpr int NC = 3 * CPP;
    extern __shared__ char smem[];
    const uint32_t sb = s2u(smem);
    const int tid = threadIdx.x, lane = tid & 31, wid = tid >> 5;
    const int m0 = blockIdx.y * 128, n0 = blockIdx.x * 128;
    const int z = blockIdx.z;

    const int lrow = tid >> 1;
    const int lseg = tid & 1;
    const bool isA = lrow < 128;
    const int grow = isA ? (m0 + lrow) : (n0 + lrow - 128);
    const size_t gbase = (size_t)z * (isA ? zA : zB) + (size_t)grow * K + lseg * 8;
    const bf16* p0 = (isA ? A0 : B0) + gbase;
    const bf16* p1 = (isA ? A1 : B1) + gbase;
    const uint32_t swr = sb + lrow * 80 + lseg * 16;

    // product order: (0,1),(1,0),(0,0) — main last
    auto selOf = [&](int p) -> int {
        return isA ? ((p == 1) ? 1 : 0) : ((p == 0) ? 1 : 0);
    };
    auto issue = [&](int cc) {
        const int p = cc / CPP, kc = cc % CPP;
        const bf16* g = ((selOf(p) == 0) ? p0 : p1) + kc * 32;
        const uint32_t st = (cc % 3) * 20480;
        cpasync16(swr + st, g);
        cpasync16(swr + st + 32, g + 16);
    };

    issue(0); CP_COMMIT();
    issue(1); CP_COMMIT();

    const int wm = (wid & 1) * 64, wn = (wid >> 1) * 16;
    uint32_t aoff[4];
#pragma unroll
    for (int mt = 0; mt < 4; mt++)
        aoff[mt] = (wm + mt * 16 + (lane & 15)) * 80 + (lane >> 4) * 16;
    const uint32_t boff = 10240 + (wn + (lane & 15)) * 80 + (lane >> 4) * 16;

    float c[4][2][4], cs[4][2][4];
#pragma unroll
    for (int i = 0; i < 4; i++)
#pragma unroll
        for (int j = 0; j < 2; j++)
#pragma unroll
            for (int e = 0; e < 4; e++) { c[i][j][e] = 0.f; cs[i][j][e] = 0.f; }

#pragma unroll 1
    for (int cc = 0; cc < NC; cc++) {
        CP_WAIT1();
        __syncthreads();
        if (cc + 2 < NC) issue(cc + 2);
        CP_COMMIT();

        const int p = cc / CPP, kc = cc % CPP;
        const bool isMain = (p == 2);
        const bool fresh = isMain ? ((kc & 1) == 0) : (kc == 0);
        const bool drain = isMain ? ((kc & 1) || kc == CPP - 1) : (kc == CPP - 1);

        if (fresh) {
#pragma unroll
            for (int i = 0; i < 4; i++)
#pragma unroll
                for (int j = 0; j < 2; j++)
#pragma unroll
                    for (int e = 0; e < 4; e++) c[i][j][e] = 0.f;
        }

        const uint32_t st = sb + (cc % 3) * 20480;
#pragma unroll
        for (int ks = 0; ks < 2; ks++) {
            uint32_t af[4][4], bfr[4];
#pragma unroll
            for (int mt = 0; mt < 4; mt++) ldsm4(af[mt], st + aoff[mt] + ks * 32);
            ldsm4(bfr, st + boff + ks * 32);
#pragma unroll
            for (int mt = 0; mt < 4; mt++)
#pragma unroll
                for (int nt = 0; nt < 2; nt++)
                    mma16816(c[mt][nt], af[mt], bfr[nt], bfr[nt + 2]);
        }

        if (drain) {
#pragma unroll
            for (int i = 0; i < 4; i++)
#pragma unroll
                for (int j = 0; j < 2; j++)
#pragma unroll
                    for (int e = 0; e < 4; e++) cs[i][j][e] += c[i][j][e];
        }
    }

#pragma unroll
    for (int mt = 0; mt < 4; mt++) {
#pragma unroll
        for (int half = 0; half < 2; half++) {
            const int m = m0 + wm + mt * 16 + (lane >> 2) + half * 8;
            int b = 0, mm = m;
            if (EPI == 1) { b = m / Lper; mm = m - b * Lper; }
#pragma unroll
            for (int nt = 0; nt < 2; nt++) {
                const int n = n0 + wn + nt * 8 + (lane & 3) * 2;
                float v0 = cs[mt][nt][half * 2 + 0];
                float v1 = cs[mt][nt][half * 2 + 1];
                if (EPI == 3) {
                    float2 fv = {v0 * 0.125f, v1 * 0.125f};
                    *reinterpret_cast<float2*>(
                        co + ((size_t)z * QLEN + m) * KVLEN + n) = fv;
                } else {
                    const float2 bb = *reinterpret_cast<const float2*>(bias + n);
                    v0 += bb.x; v1 += bb.y;
                    if (EPI == 2) {
                        float2 fv = {v0, v1};
                        *reinterpret_cast<float2*>(co + (size_t)m * HID + n) = fv;
                    } else {
                        const int h = n >> 6, d = n & 63;
                        float2 fv = {v0, v1};
                        *reinterpret_cast<float2*>(
                            co + (((size_t)b * NHEAD + h) * Lper + mm) * 64 + d) = fv;
                    }
                }
            }
        }
    }
}

// ---------------------------------------------------------------------------
// Warp reductions
// ---------------------------------------------------------------------------
__device__ __forceinline__ float warp_min(float v) {
#pragma unroll
    for (int o = 16; o; o >>= 1) v = fminf(v, __shfl_xor_sync(FULLMASK, v, o));
    return v;
}
__device__ __forceinline__ float warp_max(float v) {
#pragma unroll
    for (int o = 16; o; o >>= 1) v = fmaxf(v, __shfl_xor_sync(FULLMASK, v, o));
    return v;
}
__device__ __forceinline__ float warp_sum(float v) {
#pragma unroll
    for (int o = 16; o; o >>= 1) v += __shfl_xor_sync(FULLMASK, v, o);
    return v;
}
__device__ __forceinline__ void warp_argmin(float v, int idx, float& mv, int& ml) {
    mv = v; ml = idx;
#pragma unroll
    for (int o = 16; o; o >>= 1) {
        const float ov = __shfl_xor_sync(FULLMASK, mv, o);
        const int   ol = __shfl_xor_sync(FULLMASK, ml, o);
        if (ov < mv || (ov == mv && ol < ml)) { mv = ov; ml = ol; }
    }
}

// ---------------------------------------------------------------------------
// Approx top-64 -> exact fp32 rescore -> exact top-32 -> softmax -> V gather
// One warp per (b,h,m) row.
// ---------------------------------------------------------------------------
__global__ __launch_bounds__(256)
void topk_attend(const float* __restrict__ scores,
                 const float* __restrict__ qf, const float* __restrict__ kf,
                 const float* __restrict__ v,
                 bf16* __restrict__ a0out, bf16* __restrict__ a1out)
{
    const int gwarp = (blockIdx.x * blockDim.x + threadIdx.x) >> 5;
    const int lane = threadIdx.x & 31;
    if (gwarp >= BH * QLEN) return;

    const int m = gwarp % QLEN;
    const int h = (gwarp / QLEN) % NHEAD;
    const int b = gwarp / (QLEN * NHEAD);
    const size_t bh = (size_t)b * NHEAD + h;

    const float* srow = scores + (size_t)gwarp * KVLEN;

    // ---- phase 1: approximate top-64 (2 slots per lane) ----
    float ls0 = srow[lane];      int li0 = lane;
    float ls1 = srow[32 + lane]; int li1 = 32 + lane;
    float curmin = warp_min(fminf(ls0, ls1));

    for (int c = 2; c < KVLEN / 32; c++) {
        const float s = srow[c * 32 + lane];
        unsigned mask = __ballot_sync(FULLMASK, s > curmin);
        while (mask) {
            const int src = __ffs(mask) - 1;
            mask &= mask - 1;
            const float cand = __shfl_sync(FULLMASK, s, src);
            if (!(cand > curmin)) continue;
            const int candidx = c * 32 + src;
            float lmin; int lslot;
            if (ls0 <= ls1) { lmin = ls0; lslot = 0; } else { lmin = ls1; lslot = 1; }
            float mv; int ml;
            warp_argmin(lmin, lane, mv, ml);
            if (lane == ml) {
                if (lslot == 0) { ls0 = cand; li0 = candidx; }
                else            { ls1 = cand; li1 = candidx; }
            }
            curmin = warp_min(fminf(ls0, ls1));
        }
    }

    // ---- phase 2: exact fp32 rescore of the 64 candidates ----
    const float* qrow = qf + (bh * QLEN + m) * 64;
    const float qa = qrow[lane], qb = qrow[lane + 32];
    const float* kbase = kf + bh * KVLEN * 64;
    float es0 = -INFINITY, es1 = -INFINITY;
#pragma unroll 1
    for (int e = 0; e < 32; e++) {
        const int i0 = __shfl_sync(FULLMASK, li0, e);
        const int i1 = __shfl_sync(FULLMASK, li1, e);
        const float* kr0 = kbase + (size_t)i0 * 64;
        const float* kr1 = kbase + (size_t)i1 * 64;
        float p0 = fmaf(qa, kr0[lane], qb * kr0[lane + 32]);
        float p1 = fmaf(qa, kr1[lane], qb * kr1[lane + 32]);
        p0 = warp_sum(p0);
        p1 = warp_sum(p1);
        if (lane == e) { es0 = p0 * 0.125f; es1 = p1 * 0.125f; }
    }

    // ---- phase 3: exact top-32 (merge slot-1 batch into slot-0 list) ----
    float curmin2 = warp_min(es0);
    {
        unsigned mask = __ballot_sync(FULLMASK, es1 > curmin2);
        while (mask) {
            const int src = __ffs(mask) - 1;
            mask &= mask - 1;
            const float cand = __shfl_sync(FULLMASK, es1, src);
            if (!(cand > curmin2)) continue;
            const int candidx = __shfl_sync(FULLMASK, li1, src);
            float mv; int ml;
            warp_argmin(es0, lane, mv, ml);
            if (lane == ml) { es0 = cand; li0 = candidx; }
            curmin2 = warp_min(es0);
        }
    }

    // ---- softmax on exact scores + V gather ----
    const float mx = warp_max(es0);
    float w = expf(es0 - mx);
    const float Z = warp_sum(w);
    w /= Z;

    const float* vb = v + bh * KVLEN * 64;
    float a0 = 0.f, a1 = 0.f;
#pragma unroll
    for (int e = 0; e < TOPK; e++) {
        const float we = __shfl_sync(FULLMASK, w, e);
        const int   ie = __shfl_sync(FULLMASK, li0, e);
        const float* vr = vb + (size_t)ie * 64;
        a0 = fmaf(we, vr[lane], a0);
        a1 = fmaf(we, vr[lane + 32], a1);
    }

    const size_t dst = ((size_t)b * QLEN + m) * HID + h * 64;
    bf16 pl0 = __float2bfloat16(a0);
    bf16 pl1 = __float2bfloat16(a1);
    a0out[dst + lane]      = pl0;
    a0out[dst + lane + 32] = pl1;
    a1out[dst + lane]      = __float2bfloat16(a0 - __bfloat162float(pl0));
    a1out[dst + lane + 32] = __float2bfloat16(a1 - __bfloat162float(pl1));
}

// ---------------------------------------------------------------------------
// Host launcher
// ---------------------------------------------------------------------------
#define GADDR(var, sym) cudaGetSymbolAddress((void**)&var, sym)

extern "C" void kernel_launch(void* const* d_in, const int* in_sizes, int n_in,
                              void* d_out, int out_size)
{
    const float* query = (const float*)d_in[0];
    const float* key   = (const float*)d_in[1];
    const float* value = (const float*)d_in[2];
    const float* Wq = (const float*)d_in[3];
    const float* bq = (const float*)d_in[4];
    const float* Wk = (const float*)d_in[5];
    const float* bk = (const float*)d_in[6];
    const float* Wv = (const float*)d_in[7];
    const float* bv = (const float*)d_in[8];
    const float* Wo = (const float*)d_in[9];
    const float* bo = (const float*)d_in[10];
    float* out = (float*)d_out;

    float *qf, *kf, *v, *sc;
    bf16 *q0, *q1, *k0, *k1, *vs0, *vs1, *wv0, *wv1, *wo0, *wo1, *at0, *at1;
    GADDR(qf, g_qf); GADDR(kf, g_kf);
    GADDR(q0, g_q0); GADDR(q1, g_q1); GADDR(k0, g_k0); GADDR(k1, g_k1);
    GADDR(vs0, g_vs0); GADDR(vs1, g_vs1);
    GADDR(wv0, g_wv0); GADDR(wv1, g_wv1);
    GADDR(wo0, g_wo0); GADDR(wo1, g_wo1);
    GADDR(at0, g_at0); GADDR(at1, g_at1);
    GADDR(v, g_v); GADDR(sc, g_scores);

    const int SMEM = 61440;
    cudaFuncSetAttribute(mma_gemm<32, 1>, cudaFuncAttributeMaxDynamicSharedMemorySize, SMEM);
    cudaFuncSetAttribute(mma_gemm<32, 2>, cudaFuncAttributeMaxDynamicSharedMemorySize, SMEM);
    cudaFuncSetAttribute(mma_gemm<2, 3>,  cudaFuncAttributeMaxDynamicSharedMemorySize, SMEM);

    // ---- splits for V/O HMMA paths ----
    split2_k<<<(MKV * HID / 4 + 255) / 256, 256>>>(value, vs0, vs1, MKV * HID / 4);
    split2_k<<<(HID * HID / 4 + 255) / 256, 256>>>(Wv, wv0, wv1, HID * HID / 4);
    split2_k<<<(HID * HID / 4 + 255) / 256, 256>>>(Wo, wo0, wo1, HID * HID / 4);

    // ---- Q/K projections: fp32 FFMA (exact-grade), fp32 + 2-split bf16 out
    gemm_qk<<<dim3(HID / 128, MQ / 128), 256>>>(query, Wq, bq, qf, q0, q1, QLEN);
    gemm_qk<<<dim3(HID / 128, MKV / 128), 256>>>(key, Wk, bk, kf, k0, k1, KVLEN);

    // ---- V projection: HMMA 2-split -> fp32 head-split
    mma_gemm<32, 1><<<dim3(8, MKV / 128), 512, SMEM>>>(
        vs0, vs1, wv0, wv1, bv, v, KVLEN, 0, 0);

    // ---- Scores (candidate-grade): HMMA 3-product -> g_scores
    mma_gemm<2, 3><<<dim3(KVLEN / 128, QLEN / 128, BH), 512, SMEM>>>(
        q0, q1, k0, k1, nullptr, sc, 0,
        (long long)QLEN * 64, (long long)KVLEN * 64);

    // ---- Top-k: approx top-64 + exact rescore + softmax + gather
    topk_attend<<<(BH * QLEN) / 8, 256>>>(sc, qf, kf, v, at0, at1);

    // ---- Output projection: HMMA 2-split -> d_out
    mma_gemm<32, 2><<<dim3(8, MQ / 128), 512, SMEM>>>(
        at0, at1, wo0, wo1, bo, out, QLEN, 0, 0);
}

// round 6
// speedup vs baseline: 1.1590x; 1.1590x over previous
#include <cuda_runtime.h>
#include <math.h>

#define FULLMASK 0xffffffffu

// Problem constants
#define BATCH 2
#define NHEAD 16
#define QLEN  2048
#define KVLEN 4096
#define HDIM  64
#define HID   1024
#define TOPK  32

// ---------------------------------------------------------------------------
// Scratch (device globals: allocation is disallowed)
// ---------------------------------------------------------------------------
__device__ float g_q[(size_t)BATCH * NHEAD * QLEN * HDIM];            // 16 MB
__device__ float g_k[(size_t)BATCH * NHEAD * KVLEN * HDIM];           // 32 MB
__device__ float g_v[(size_t)BATCH * NHEAD * KVLEN * HDIM];           // 32 MB
__device__ float g_attn[(size_t)BATCH * QLEN * HID];                  // 16 MB
__device__ float g_scores[(size_t)BATCH * NHEAD * QLEN * KVLEN];      // 1.07 GB

// ---------------------------------------------------------------------------
// NT GEMM: C[m,n] = scale * sum_k A[m,k]*B[n,k] + bias[n]
// A: [M,K] row-major, B: [N,K] row-major.
// mode 0: C[m*N+n];  mode 1: head-split store.
// Batched via blockIdx.z with strides sA,sB,sC.
// Tile 128x128, Kstep 16, 256 threads, 8x8 micro-tile.
// Register double-buffer: chunk k+1's global loads issued before chunk k's
// compute (accumulation order — and thus all results — bitwise unchanged).
// ---------------------------------------------------------------------------
__global__ __launch_bounds__(256, 2)
void gemm_nt(const float* __restrict__ A, const float* __restrict__ Bm,
             const float* __restrict__ bias, float* __restrict__ C,
             int M, int N, int K,
             long long sA, long long sB, long long sC,
             float scale, int mode, int Lper)
{
    const int z = blockIdx.z;
    A  += (size_t)z * sA;
    Bm += (size_t)z * sB;
    C  += (size_t)z * sC;

    __shared__ float As[16][132];
    __shared__ float Bs[16][132];

    const int tid = threadIdx.x;
    const int tx = tid & 15;        // 0..15 -> columns
    const int ty = tid >> 4;        // 0..15 -> rows
    const int m0 = blockIdx.y * 128;
    const int n0 = blockIdx.x * 128;

    // load mapping: each thread loads 8 consecutive floats of one row
    const int lrow = tid >> 1;          // 0..127
    const int lcol = (tid & 1) * 8;     // 0 or 8

    float acc[8][8];
#pragma unroll
    for (int i = 0; i < 8; i++)
#pragma unroll
        for (int j = 0; j < 8; j++) acc[i][j] = 0.f;

    const float* agp = A  + (size_t)(m0 + lrow) * K + lcol;
    const float* bgp = Bm + (size_t)(n0 + lrow) * K + lcol;

    // prefetch chunk 0
    float4 ra0 = *(const float4*)(agp);
    float4 ra1 = *(const float4*)(agp + 4);
    float4 rb0 = *(const float4*)(bgp);
    float4 rb1 = *(const float4*)(bgp + 4);

    for (int k0 = 0; k0 < K; k0 += 16) {
        __syncthreads();   // previous tile fully consumed
        As[lcol + 0][lrow] = ra0.x; As[lcol + 1][lrow] = ra0.y;
        As[lcol + 2][lrow] = ra0.z; As[lcol + 3][lrow] = ra0.w;
        As[lcol + 4][lrow] = ra1.x; As[lcol + 5][lrow] = ra1.y;
        As[lcol + 6][lrow] = ra1.z; As[lcol + 7][lrow] = ra1.w;
        Bs[lcol + 0][lrow] = rb0.x; Bs[lcol + 1][lrow] = rb0.y;
        Bs[lcol + 2][lrow] = rb0.z; Bs[lcol + 3][lrow] = rb0.w;
        Bs[lcol + 4][lrow] = rb1.x; Bs[lcol + 5][lrow] = rb1.y;
        Bs[lcol + 6][lrow] = rb1.z; Bs[lcol + 7][lrow] = rb1.w;
        __syncthreads();

        // issue next chunk's global loads early; FFMA below hides them
        if (k0 + 16 < K) {
            ra0 = *(const float4*)(agp + k0 + 16);
            ra1 = *(const float4*)(agp + k0 + 20);
            rb0 = *(const float4*)(bgp + k0 + 16);
            rb1 = *(const float4*)(bgp + k0 + 20);
        }

#pragma unroll
        for (int kk = 0; kk < 16; kk++) {
            float4 xa0 = *(const float4*)&As[kk][ty * 4];
            float4 xa1 = *(const float4*)&As[kk][64 + ty * 4];
            float4 xb0 = *(const float4*)&Bs[kk][tx * 4];
            float4 xb1 = *(const float4*)&Bs[kk][64 + tx * 4];
            float av[8], bv[8];
            av[0] = xa0.x; av[1] = xa0.y; av[2] = xa0.z; av[3] = xa0.w;
            av[4] = xa1.x; av[5] = xa1.y; av[6] = xa1.z; av[7] = xa1.w;
            bv[0] = xb0.x; bv[1] = xb0.y; bv[2] = xb0.z; bv[3] = xb0.w;
            bv[4] = xb1.x; bv[5] = xb1.y; bv[6] = xb1.z; bv[7] = xb1.w;
#pragma unroll
            for (int i = 0; i < 8; i++)
#pragma unroll
                for (int j = 0; j < 8; j++)
                    acc[i][j] = fmaf(av[i], bv[j], acc[i][j]);
        }
    }

    // epilogue
#pragma unroll
    for (int i = 0; i < 8; i++) {
        const int m = m0 + ((i < 4) ? (ty * 4 + i) : (64 + ty * 4 + (i - 4)));
#pragma unroll
        for (int j = 0; j < 8; j++) {
            const int n = n0 + ((j < 4) ? (tx * 4 + j) : (64 + tx * 4 + (j - 4)));
            float val = acc[i][j] * scale;
            if (bias) val += bias[n];
            if (mode == 0) {
                C[(size_t)m * N + n] = val;
            } else {
                const int bb = m / Lper;
                const int mm = m - bb * Lper;
                const int h = n >> 6;
                const int d = n & 63;
                C[(((size_t)bb * NHEAD + h) * Lper + mm) * 64 + d] = val;
            }
        }
    }
}

// ---------------------------------------------------------------------------
// Warp reductions
// ---------------------------------------------------------------------------
__device__ __forceinline__ float warp_min(float v) {
#pragma unroll
    for (int o = 16; o; o >>= 1) v = fminf(v, __shfl_xor_sync(FULLMASK, v, o));
    return v;
}
__device__ __forceinline__ float warp_max(float v) {
#pragma unroll
    for (int o = 16; o; o >>= 1) v = fmaxf(v, __shfl_xor_sync(FULLMASK, v, o));
    return v;
}
__device__ __forceinline__ float warp_sum(float v) {
#pragma unroll
    for (int o = 16; o; o >>= 1) v += __shfl_xor_sync(FULLMASK, v, o);
    return v;
}
__device__ __forceinline__ void warp_argmin(float v, int idx, float& mv, int& ml) {
    mv = v; ml = idx;
#pragma unroll
    for (int o = 16; o; o >>= 1) {
        const float ov = __shfl_xor_sync(FULLMASK, mv, o);
        const int   ol = __shfl_xor_sync(FULLMASK, ml, o);
        if (ov < mv || (ov == mv && ol < ml)) { mv = ov; ml = ol; }
    }
}

// ---------------------------------------------------------------------------
// Top-32 + softmax + V gather. One warp per (b,h,m) row.
// Prune with a stale (lower-bound) threshold; validate each candidate against
// the fresh list-min from the argmin before replacing — identical top-32 set
// to the exact algorithm, ~half the shuffle work per insert.
// ---------------------------------------------------------------------------
__global__ __launch_bounds__(256)
void topk_attend(const float* __restrict__ scores, const float* __restrict__ v,
                 float* __restrict__ attn)
{
    const int gwarp = (blockIdx.x * blockDim.x + threadIdx.x) >> 5;
    const int lane = threadIdx.x & 31;
    if (gwarp >= BATCH * NHEAD * QLEN) return;

    const int m = gwarp % QLEN;
    const int h = (gwarp / QLEN) % NHEAD;
    const int b = gwarp / (QLEN * NHEAD);

    const float* srow = scores + (size_t)gwarp * KVLEN;

    float ls = srow[lane];
    int   li = lane;
    float curmin = warp_min(ls);   // fresh

    for (int c = 1; c < KVLEN / 32; c++) {
        const float s = srow[c * 32 + lane];
        unsigned mask = __ballot_sync(FULLMASK, s > curmin);
        if (!mask) continue;
        do {
            const int src = __ffs(mask) - 1;
            mask &= mask - 1;
            const float cand = __shfl_sync(FULLMASK, s, src);
            float mv; int ml;
            warp_argmin(ls, lane, mv, ml);        // fresh list minimum
            if (cand > mv) {
                if (lane == ml) { ls = cand; li = c * 32 + src; }
            }
        } while (mask);
        curmin = warp_min(ls);   // refresh once per chunk that had candidates
    }

    // softmax over the 32 kept scores
    const float mx = warp_max(ls);
    float w = expf(ls - mx);
    const float Z = warp_sum(w);
    w /= Z;

    // gather V rows (head-split layout [B,NH,KV,64]) and accumulate
    const float* vb = v + ((size_t)(b * NHEAD + h)) * KVLEN * HDIM;
    float a0 = 0.f, a1 = 0.f;
#pragma unroll
    for (int e = 0; e < TOPK; e++) {
        const float we = __shfl_sync(FULLMASK, w, e);
        const int   ie = __shfl_sync(FULLMASK, li, e);
        const float* vr = vb + (size_t)ie * HDIM;
        a0 = fmaf(we, vr[lane], a0);
        a1 = fmaf(we, vr[lane + 32], a1);
    }

    float* dst = attn + ((size_t)b * QLEN + m) * HID + h * HDIM;
    dst[lane] = a0;
    dst[lane + 32] = a1;
}

// ---------------------------------------------------------------------------
// Host launcher
// ---------------------------------------------------------------------------
extern "C" void kernel_launch(void* const* d_in, const int* in_sizes, int n_in,
                              void* d_out, int out_size)
{
    const float* query = (const float*)d_in[0];
    const float* key   = (const float*)d_in[1];
    const float* value = (const float*)d_in[2];
    const float* Wq = (const float*)d_in[3];
    const float* bq = (const float*)d_in[4];
    const float* Wk = (const float*)d_in[5];
    const float* bk = (const float*)d_in[6];
    const float* Wv = (const float*)d_in[7];
    const float* bv = (const float*)d_in[8];
    const float* Wo = (const float*)d_in[9];
    const float* bo = (const float*)d_in[10];
    float* out = (float*)d_out;

    float *q, *k, *v, *attn, *sc;
    cudaGetSymbolAddress((void**)&q, g_q);
    cudaGetSymbolAddress((void**)&k, g_k);
    cudaGetSymbolAddress((void**)&v, g_v);
    cudaGetSymbolAddress((void**)&attn, g_attn);
    cudaGetSymbolAddress((void**)&sc, g_scores);

    const dim3 blk(256);

    // Q projection: [4096,1024] @ Wq^T, head-split store into g_q
    gemm_nt<<<dim3(HID / 128, (BATCH * QLEN) / 128, 1), blk>>>(
        query, Wq, bq, q, BATCH * QLEN, HID, HID, 0, 0, 0, 1.f, 1, QLEN);

    // K projection: [8192,1024] @ Wk^T -> g_k
    gemm_nt<<<dim3(HID / 128, (BATCH * KVLEN) / 128, 1), blk>>>(
        key, Wk, bk, k, BATCH * KVLEN, HID, HID, 0, 0, 0, 1.f, 1, KVLEN);

    // V projection -> g_v
    gemm_nt<<<dim3(HID / 128, (BATCH * KVLEN) / 128, 1), blk>>>(
        value, Wv, bv, v, BATCH * KVLEN, HID, HID, 0, 0, 0, 1.f, 1, KVLEN);

    // Scores: per (b,h): [2048,64] @ [4096,64]^T / 8 -> g_scores
    gemm_nt<<<dim3(KVLEN / 128, QLEN / 128, BATCH * NHEAD), blk>>>(
        q, k, nullptr, sc, QLEN, KVLEN, HDIM,
        (long long)QLEN * HDIM, (long long)KVLEN * HDIM, (long long)QLEN * KVLEN,
        0.125f, 0, 0);

    // Top-k + softmax + gather: one warp per row
    topk_attend<<<(BATCH * NHEAD * QLEN) / 8, blk>>>(sc, v, attn);

    // Output projection -> d_out
    gemm_nt<<<dim3(HID / 128, (BATCH * QLEN) / 128, 1), blk>>>(
        attn, Wo, bo, out, BATCH * QLEN, HID, HID, 0, 0, 0, 1.f, 0, 0);
}